// round 10
// baseline (speedup 1.0000x reference)
#include <cuda_runtime.h>

// SSIM-style loss (sum over channels+window, /ws^2), single fused kernel.
// x, y: (32, 3, 512, 512) fp32. out: (32,) fp32.
//
// R10: finest one-wave decomposition. Grid 4096 = (batch, window-row,
// col-quarter); 64 threads = (row-half hh, float4-col t in 32-wide quarter).
// Per-thread work same as R9 (8 rows x 3 ch, 24 LDG.128/input); warp request
// = 512B contiguous. 28 CTA/SM (4144 slots >= 4096, one wave), per-CTA time
// halves -> wave-exit straggler tail halves (the R9 win mechanism).
// 8 windows per CTA, all intra-CTA; ticket counts 128 CTAs/batch.

#define IMG_H 512
#define IMG_W 512
#define NCH 3
#define WS 16
#define NWIN_X 32
#define NWIN_Y 32
#define NBATCH 32
#define W4 (IMG_W / 4)
#define CTAS_PER_BATCH (NWIN_Y * 4)     // 128

static __device__ float        g_partial[NBATCH * CTAS_PER_BATCH];
static __device__ unsigned int g_ticket[NBATCH];

__global__ __launch_bounds__(64, 28)
void ssim_fused_kernel(const float* __restrict__ x, const float* __restrict__ y,
                       float* __restrict__ out) {
    const int tid = threadIdx.x;
    const int hh  = tid >> 5;               // row half: rows 0..7 / 8..15
    const int t   = tid & 31;               // float4 col within quarter, 0..31
    const int cq  = blockIdx.x & 3;         // column quarter
    const int br  = (blockIdx.x >> 2) & 31; // window row
    const int b   = blockIdx.x >> 7;        // batch

    const size_t img = (size_t)NCH * IMG_H * IMG_W;
    const float4* __restrict__ xp = (const float4*)(x + (size_t)b * img);
    const float4* __restrict__ yp = (const float4*)(y + (size_t)b * img);

    const int col4 = (cq << 5) + t;          // global float4 column 0..127

    float sx = 0.f, sy = 0.f, sxx = 0.f, syy = 0.f, sxy = 0.f;

#pragma unroll
    for (int c = 0; c < NCH; ++c) {
        size_t base = (size_t)c * (IMG_H * W4)
                    + (size_t)(br * WS + hh * 8) * W4 + col4;
#pragma unroll
        for (int h0 = 0; h0 < 8; h0 += 2) {
            float4 vx0 = __ldcs(xp + base + (size_t)(h0    ) * W4);
            float4 vx1 = __ldcs(xp + base + (size_t)(h0 + 1) * W4);
            float4 vy0 = __ldcs(yp + base + (size_t)(h0    ) * W4);
            float4 vy1 = __ldcs(yp + base + (size_t)(h0 + 1) * W4);

            sx += (vx0.x + vx0.y) + (vx0.z + vx0.w);
            sy += (vy0.x + vy0.y) + (vy0.z + vy0.w);
            sxx = fmaf(vx0.x, vx0.x, sxx); sxx = fmaf(vx0.y, vx0.y, sxx);
            sxx = fmaf(vx0.z, vx0.z, sxx); sxx = fmaf(vx0.w, vx0.w, sxx);
            syy = fmaf(vy0.x, vy0.x, syy); syy = fmaf(vy0.y, vy0.y, syy);
            syy = fmaf(vy0.z, vy0.z, syy); syy = fmaf(vy0.w, vy0.w, syy);
            sxy = fmaf(vx0.x, vy0.x, sxy); sxy = fmaf(vx0.y, vy0.y, sxy);
            sxy = fmaf(vx0.z, vy0.z, sxy); sxy = fmaf(vx0.w, vy0.w, sxy);

            sx += (vx1.x + vx1.y) + (vx1.z + vx1.w);
            sy += (vy1.x + vy1.y) + (vy1.z + vy1.w);
            sxx = fmaf(vx1.x, vx1.x, sxx); sxx = fmaf(vx1.y, vx1.y, sxx);
            sxx = fmaf(vx1.z, vx1.z, sxx); sxx = fmaf(vx1.w, vx1.w, sxx);
            syy = fmaf(vy1.x, vy1.x, syy); syy = fmaf(vy1.y, vy1.y, syy);
            syy = fmaf(vy1.z, vy1.z, syy); syy = fmaf(vy1.w, vy1.w, syy);
            sxy = fmaf(vx1.x, vy1.x, sxy); sxy = fmaf(vx1.y, vy1.y, sxy);
            sxy = fmaf(vx1.z, vy1.z, sxy); sxy = fmaf(vx1.w, vy1.w, sxy);
        }
    }

    // fold 4 adjacent lanes (16 cols = one window, this row-half)
#pragma unroll
    for (int off = 1; off < 4; off <<= 1) {
        sx  += __shfl_xor_sync(0xffffffffu, sx,  off);
        sy  += __shfl_xor_sync(0xffffffffu, sy,  off);
        sxx += __shfl_xor_sync(0xffffffffu, sxx, off);
        syy += __shfl_xor_sync(0xffffffffu, syy, off);
        sxy += __shfl_xor_sync(0xffffffffu, sxy, off);
    }

    __shared__ float s_sums[2][8][5];        // [row-half][window-in-quarter][stat]
    __shared__ unsigned int s_ticket;
    if ((t & 3) == 0) {
        const int win = t >> 2;              // 0..7
        s_sums[hh][win][0] = sx;
        s_sums[hh][win][1] = sy;
        s_sums[hh][win][2] = sxx;
        s_sums[hh][win][3] = syy;
        s_sums[hh][win][4] = sxy;
    }
    __syncthreads();

    if (tid < 8) {
        float S0 = s_sums[0][tid][0] + s_sums[1][tid][0];
        float S1 = s_sums[0][tid][1] + s_sums[1][tid][1];
        float S2 = s_sums[0][tid][2] + s_sums[1][tid][2];
        float S3 = s_sums[0][tid][3] + s_sums[1][tid][3];
        float S4 = s_sums[0][tid][4] + s_sums[1][tid][4];

        const float inv = 1.0f / (WS * WS);
        const float C1 = 6.5025f;
        const float C2 = 58.5225f;
        float mx = S0 * inv, my = S1 * inv;
        float vx = S2 * inv - mx * mx;
        float vy = S3 * inv - my * my;
        float cv = S4 * inv - mx * my;
        float num = (2.0f * mx * my + C1) * (2.0f * cv + C2);
        float den = (mx * mx + my * my + C1) * (vx + vy + C2);
        float v = num / den;

#pragma unroll
        for (int off = 4; off; off >>= 1)
            v += __shfl_xor_sync(0x000000ffu, v, off);
        if (tid == 0) {
            g_partial[blockIdx.x] = v;
            __threadfence();
            unsigned int tk = atomicAdd(&g_ticket[b], 1u);
            s_ticket = tk;
        }
    }
    __syncthreads();

    // Last CTA of this batch folds the 128 partials.
    if (s_ticket == CTAS_PER_BATCH - 1) {
        if (tid < 32) {
            volatile float* vp = (volatile float*)&g_partial[b * CTAS_PER_BATCH];
            float v = (vp[tid] + vp[tid + 32]) + (vp[tid + 64] + vp[tid + 96]);
#pragma unroll
            for (int off = 16; off; off >>= 1)
                v += __shfl_xor_sync(0xffffffffu, v, off);
            if (tid == 0) {
                out[b] = (1.0f - v * (1.0f / (NWIN_X * NWIN_Y))) * 0.5f;
                g_ticket[b] = 0u;   // reset for next (graph-replayed) launch
            }
        }
    }
}

extern "C" void kernel_launch(void* const* d_in, const int* in_sizes, int n_in,
                              void* d_out, int out_size) {
    const float* x = (const float*)d_in[0];
    const float* y = (const float*)d_in[1];
    float* out = (float*)d_out;
    (void)in_sizes; (void)n_in; (void)out_size;

    ssim_fused_kernel<<<NBATCH * CTAS_PER_BATCH, 64>>>(x, y, out);
}

// round 11
// speedup vs baseline: 1.0082x; 1.0082x over previous
#include <cuda_runtime.h>

// SSIM-style loss (sum over channels+window, /ws^2), single fused kernel.
// x, y: (32, 3, 512, 512) fp32. out: (32,) fp32.
//
// Best-measured config (R9): grid 2048 = (batch, window-row, col-half);
// 128 threads = (row-half hh, float4-col t within the 64-wide half).
// Each thread streams 8 rows x 3 channels (24 LDG.128 per input).
// 14 CTA/SM, one wave. Every 16x16 window fully inside one CTA.
// Epilogue: release-scoped ticket atomic (no separate MEMBAR), acquire reads
// on the last-CTA fold. Ticket resets itself for graph replay.

#define IMG_H 512
#define IMG_W 512
#define NCH 3
#define WS 16
#define NWIN_X 32
#define NWIN_Y 32
#define NBATCH 32
#define W4 (IMG_W / 4)
#define CTAS_PER_BATCH (NWIN_Y * 2)     // 64

static __device__ float        g_partial[NBATCH * CTAS_PER_BATCH];
static __device__ unsigned int g_ticket[NBATCH];

__device__ __forceinline__ unsigned int atom_add_release(unsigned int* p, unsigned int v) {
    unsigned int old;
    asm volatile("atom.release.gpu.global.add.u32 %0, [%1], %2;"
                 : "=r"(old) : "l"(p), "r"(v) : "memory");
    return old;
}

__device__ __forceinline__ float ld_acquire_f32(const float* p) {
    float v;
    asm volatile("ld.acquire.gpu.global.f32 %0, [%1];" : "=f"(v) : "l"(p) : "memory");
    return v;
}

__global__ __launch_bounds__(128, 14)
void ssim_fused_kernel(const float* __restrict__ x, const float* __restrict__ y,
                       float* __restrict__ out) {
    const int tid = threadIdx.x;
    const int hh  = tid >> 6;              // row half: rows 0..7 / 8..15
    const int t   = tid & 63;              // float4 col within half, 0..63
    const int ch  = blockIdx.x & 1;        // column half
    const int br  = (blockIdx.x >> 1) & 31;// window row
    const int b   = blockIdx.x >> 6;       // batch

    const size_t img = (size_t)NCH * IMG_H * IMG_W;
    const float4* __restrict__ xp = (const float4*)(x + (size_t)b * img);
    const float4* __restrict__ yp = (const float4*)(y + (size_t)b * img);

    const int col4 = (ch << 6) + t;        // global float4 column 0..127

    float sx = 0.f, sy = 0.f, sxx = 0.f, syy = 0.f, sxy = 0.f;

#pragma unroll
    for (int c = 0; c < NCH; ++c) {
        size_t base = (size_t)c * (IMG_H * W4)
                    + (size_t)(br * WS + hh * 8) * W4 + col4;
#pragma unroll
        for (int h0 = 0; h0 < 8; h0 += 2) {
            float4 vx0 = __ldcs(xp + base + (size_t)(h0    ) * W4);
            float4 vx1 = __ldcs(xp + base + (size_t)(h0 + 1) * W4);
            float4 vy0 = __ldcs(yp + base + (size_t)(h0    ) * W4);
            float4 vy1 = __ldcs(yp + base + (size_t)(h0 + 1) * W4);

            sx += (vx0.x + vx0.y) + (vx0.z + vx0.w);
            sy += (vy0.x + vy0.y) + (vy0.z + vy0.w);
            sxx = fmaf(vx0.x, vx0.x, sxx); sxx = fmaf(vx0.y, vx0.y, sxx);
            sxx = fmaf(vx0.z, vx0.z, sxx); sxx = fmaf(vx0.w, vx0.w, sxx);
            syy = fmaf(vy0.x, vy0.x, syy); syy = fmaf(vy0.y, vy0.y, syy);
            syy = fmaf(vy0.z, vy0.z, syy); syy = fmaf(vy0.w, vy0.w, syy);
            sxy = fmaf(vx0.x, vy0.x, sxy); sxy = fmaf(vx0.y, vy0.y, sxy);
            sxy = fmaf(vx0.z, vy0.z, sxy); sxy = fmaf(vx0.w, vy0.w, sxy);

            sx += (vx1.x + vx1.y) + (vx1.z + vx1.w);
            sy += (vy1.x + vy1.y) + (vy1.z + vy1.w);
            sxx = fmaf(vx1.x, vx1.x, sxx); sxx = fmaf(vx1.y, vx1.y, sxx);
            sxx = fmaf(vx1.z, vx1.z, sxx); sxx = fmaf(vx1.w, vx1.w, sxx);
            syy = fmaf(vy1.x, vy1.x, syy); syy = fmaf(vy1.y, vy1.y, syy);
            syy = fmaf(vy1.z, vy1.z, syy); syy = fmaf(vy1.w, vy1.w, syy);
            sxy = fmaf(vx1.x, vy1.x, sxy); sxy = fmaf(vx1.y, vy1.y, sxy);
            sxy = fmaf(vx1.z, vy1.z, sxy); sxy = fmaf(vx1.w, vy1.w, sxy);
        }
    }

    // fold 4 adjacent threads (16 cols = one window, this row-half)
#pragma unroll
    for (int off = 1; off < 4; off <<= 1) {
        sx  += __shfl_xor_sync(0xffffffffu, sx,  off);
        sy  += __shfl_xor_sync(0xffffffffu, sy,  off);
        sxx += __shfl_xor_sync(0xffffffffu, sxx, off);
        syy += __shfl_xor_sync(0xffffffffu, syy, off);
        sxy += __shfl_xor_sync(0xffffffffu, sxy, off);
    }

    __shared__ float s_sums[2][16][5];     // [row-half][window-in-half][stat]
    __shared__ unsigned int s_ticket;
    if ((t & 3) == 0) {
        const int win = t >> 2;            // 0..15
        s_sums[hh][win][0] = sx;
        s_sums[hh][win][1] = sy;
        s_sums[hh][win][2] = sxx;
        s_sums[hh][win][3] = syy;
        s_sums[hh][win][4] = sxy;
    }
    __syncthreads();

    if (tid < 16) {
        float S0 = s_sums[0][tid][0] + s_sums[1][tid][0];
        float S1 = s_sums[0][tid][1] + s_sums[1][tid][1];
        float S2 = s_sums[0][tid][2] + s_sums[1][tid][2];
        float S3 = s_sums[0][tid][3] + s_sums[1][tid][3];
        float S4 = s_sums[0][tid][4] + s_sums[1][tid][4];

        const float inv = 1.0f / (WS * WS);
        const float C1 = 6.5025f;
        const float C2 = 58.5225f;
        float mx = S0 * inv, my = S1 * inv;
        float vx = S2 * inv - mx * mx;
        float vy = S3 * inv - my * my;
        float cv = S4 * inv - mx * my;
        float num = (2.0f * mx * my + C1) * (2.0f * cv + C2);
        float den = (mx * mx + my * my + C1) * (vx + vy + C2);
        float v = num / den;

#pragma unroll
        for (int off = 8; off; off >>= 1)
            v += __shfl_xor_sync(0x0000ffffu, v, off);
        if (tid == 0) {
            g_partial[blockIdx.x] = v;
            // release-scoped increment orders the partial store before the
            // ticket becomes visible (no separate MEMBAR.GPU).
            s_ticket = atom_add_release(&g_ticket[b], 1u);
        }
    }
    __syncthreads();

    // Last CTA of this batch folds the 64 partials.
    if (s_ticket == CTAS_PER_BATCH - 1) {
        if (tid < 32) {
            float v = ld_acquire_f32(&g_partial[b * CTAS_PER_BATCH + tid])
                    + ld_acquire_f32(&g_partial[b * CTAS_PER_BATCH + tid + 32]);
#pragma unroll
            for (int off = 16; off; off >>= 1)
                v += __shfl_xor_sync(0xffffffffu, v, off);
            if (tid == 0) {
                out[b] = (1.0f - v * (1.0f / (NWIN_X * NWIN_Y))) * 0.5f;
                g_ticket[b] = 0u;   // reset for next (graph-replayed) launch
            }
        }
    }
}

extern "C" void kernel_launch(void* const* d_in, const int* in_sizes, int n_in,
                              void* d_out, int out_size) {
    const float* x = (const float*)d_in[0];
    const float* y = (const float*)d_in[1];
    float* out = (float*)d_out;
    (void)in_sizes; (void)n_in; (void)out_size;

    ssim_fused_kernel<<<NBATCH * CTAS_PER_BATCH, 128>>>(x, y, out);
}